// round 16
// baseline (speedup 1.0000x reference)
#include <cuda_runtime.h>
#include <cstdint>

// Problem constants (fixed by the reference)
#define BB 8
#define TT 512
#define DD 512
#define D4 (DD / 4)        // 128 float4 per frame
#define MAX_LEN 7680       // TT * 15
#define FR 32              // output frames per window
#define NWIN (MAX_LEN / FR)  // 240 windows per batch
#define NSEGX 74           // CTAs per batch (74*8 = 592 = one full wave)

// ---------------------------------------------------------------------------
// Persistent fused kernel. Grid (74, 8), block 512 — exactly one wave.
//   Scan ONCE per CTA: shfl block-scan of max(dur,1); thread t keeps
//   [start,end) in registers.
//   Then loop over windows w = seg, seg+74, ... (3-4 per CTA):
//     scatter t into sidx for owned frames inside the window (-1 elsewhere),
//     gather-expand 8 frames/thread with front-batched loads + streaming
//     stores.
// ---------------------------------------------------------------------------
__global__ void __launch_bounds__(512) fused_expand_kernel(
    const float4* __restrict__ feat,  // (B, T, D/4)
    const int*    __restrict__ dur,   // (B, T)
    float4*       __restrict__ out)   // (B, MAX_LEN, D/4)
{
    __shared__ int wsum[16];
    __shared__ int sidx[FR];

    const int b   = blockIdx.y;
    const int seg = blockIdx.x;             // 0..NSEGX-1
    const int tid = threadIdx.x;            // 0..511
    const int lane5 = tid & 31, w = tid >> 5;

    // ---- Scan (once per CTA): inclusive cumsum of clamped durations ----
    int v = __ldg(&dur[b * TT + tid]);
    v = (v < 1) ? 1 : v;
    int x = v;
#pragma unroll
    for (int o = 1; o < 32; o <<= 1) {
        int y = __shfl_up_sync(0xFFFFFFFFu, x, o);
        if (lane5 >= o) x += y;
    }
    if (lane5 == 31) wsum[w] = x;
    __syncthreads();
    if (w == 0) {
        int s = (lane5 < 16) ? wsum[lane5] : 0;
#pragma unroll
        for (int o = 1; o < 16; o <<= 1) {
            int y = __shfl_up_sync(0xFFFFFFFFu, s, o);
            if (lane5 >= o) s += y;
        }
        if (lane5 < 16) wsum[lane5] = s;
    }
    __syncthreads();
    const int end   = ((w > 0) ? wsum[w - 1] : 0) + x;  // inclusive cumsum
    const int start = end - v;

    const int y    = tid >> 7;   // 0..3 (group)
    const int lane = tid & 127;  // 0..127
    const float4* __restrict__ fb = feat + (size_t)b * TT * D4;
    const float4 zero = make_float4(0.f, 0.f, 0.f, 0.f);

    // ---- Window loop (3-4 windows per CTA) ----
    for (int wx = seg; wx < NWIN; wx += NSEGX) {
        const int base0 = wx * FR;

        // init + scatter
        if (tid < FR) sidx[tid] = -1;
        __syncthreads();
        {
            int lo = (start > base0) ? start : base0;
            const int hi = (end < base0 + FR) ? end : (base0 + FR);
            for (int i = lo; i < hi; i++) sidx[i - base0] = tid;
        }
        __syncthreads();

        // read indices into registers, then release sidx for next window
        int idx[8];
#pragma unroll
        for (int j = 0; j < 8; j++)
            idx[j] = sidx[y + 4 * j];
        __syncthreads();

        // front-batched gather loads, then stores
        float4 val[8];
#pragma unroll
        for (int j = 0; j < 8; j++)
            val[j] = (idx[j] >= 0) ? __ldg(fb + (size_t)idx[j] * D4 + lane)
                                   : zero;

        float4* __restrict__ ob =
            out + ((size_t)b * MAX_LEN + base0 + y) * D4 + lane;
#pragma unroll
        for (int j = 0; j < 8; j++)
            __stcs(&ob[(size_t)4 * j * D4], val[j]);
    }
}

// ---------------------------------------------------------------------------
// Launch
// ---------------------------------------------------------------------------
extern "C" void kernel_launch(void* const* d_in, const int* in_sizes, int n_in,
                              void* d_out, int out_size) {
    const float4* feat = (const float4*)d_in[0];  // features (8,512,512) f32
    const int*    dur  = (const int*)d_in[1];     // durations (8,512) i32
    float4*       out  = (float4*)d_out;          // (8,7680,512) f32

    (void)in_sizes; (void)n_in; (void)out_size;

    dim3 grid(NSEGX, BB, 1);
    fused_expand_kernel<<<grid, 512>>>(feat, dur, out);
}

// round 17
// speedup vs baseline: 1.0118x; 1.0118x over previous
#include <cuda_runtime.h>
#include <cstdint>

// Problem constants (fixed by the reference)
#define BB 8
#define TT 512
#define DD 512
#define MAX_LEN 7680      // TT * 15
#define FR 32             // output frames per CTA

// 256-bit global memory helpers (sm_100+: LDG.E.256 / STG.E.256)
struct f32x8 { float v[8]; };

__device__ __forceinline__ f32x8 ldg256(const float* p) {
    f32x8 r;
    asm volatile(
        "ld.global.nc.v8.f32 {%0,%1,%2,%3,%4,%5,%6,%7}, [%8];"
        : "=f"(r.v[0]), "=f"(r.v[1]), "=f"(r.v[2]), "=f"(r.v[3]),
          "=f"(r.v[4]), "=f"(r.v[5]), "=f"(r.v[6]), "=f"(r.v[7])
        : "l"(p));
    return r;
}

__device__ __forceinline__ void stg256(float* p, const f32x8& r) {
    asm volatile(
        "st.global.cs.v8.f32 [%0], {%1,%2,%3,%4,%5,%6,%7,%8};"
        :: "l"(p),
           "f"(r.v[0]), "f"(r.v[1]), "f"(r.v[2]), "f"(r.v[3]),
           "f"(r.v[4]), "f"(r.v[5]), "f"(r.v[6]), "f"(r.v[7])
        : "memory");
}

// ---------------------------------------------------------------------------
// Single fused kernel. Grid (240, 8), block 512.
//   Phase 1: shfl block-scan of max(dur,1); thread t keeps [start,end).
//   Phase 2: scatter — thread t writes t into sidx for frames it owns inside
//            this CTA's 32-frame window (frames past total keep -1).
//   Phase 3: gather-expand with 256-bit accesses: 64 lanes per frame,
//            32 B per lane; 8 groups x 4 frames/thread; all 4 LDG.256
//            front-batched, then 4 STG.256.
// ---------------------------------------------------------------------------
__global__ void __launch_bounds__(512) fused_expand_kernel(
    const float* __restrict__ feat,   // (B, T, D)
    const int*   __restrict__ dur,    // (B, T)
    float*       __restrict__ out)    // (B, MAX_LEN, D)
{
    __shared__ int wsum[16];
    __shared__ int sidx[FR];

    const int b     = blockIdx.y;
    const int base0 = blockIdx.x * FR;
    const int tid   = threadIdx.x;          // 0..511
    const int lane5 = tid & 31, w = tid >> 5;

    // Pre-init sidx (ordered before the scatter by the scan barriers).
    if (tid < FR) sidx[tid] = -1;

    // ---- Phase 1: inclusive scan of clamped durations ----
    int v = __ldg(&dur[b * TT + tid]);
    v = (v < 1) ? 1 : v;
    int x = v;
#pragma unroll
    for (int o = 1; o < 32; o <<= 1) {
        int y = __shfl_up_sync(0xFFFFFFFFu, x, o);
        if (lane5 >= o) x += y;
    }
    if (lane5 == 31) wsum[w] = x;
    __syncthreads();
    if (w == 0) {
        int s = (lane5 < 16) ? wsum[lane5] : 0;
#pragma unroll
        for (int o = 1; o < 16; o <<= 1) {
            int y = __shfl_up_sync(0xFFFFFFFFu, s, o);
            if (lane5 >= o) s += y;
        }
        if (lane5 < 16) wsum[lane5] = s;
    }
    __syncthreads();
    const int end   = ((w > 0) ? wsum[w - 1] : 0) + x;  // inclusive cumsum
    const int start = end - v;

    // ---- Phase 2: scatter phoneme id into this CTA's frame window ----
    {
        int lo = (start > base0) ? start : base0;
        const int hi = (end < base0 + FR) ? end : (base0 + FR);
        for (int i = lo; i < hi; i++) sidx[i - base0] = tid;
    }
    __syncthreads();

    // ---- Phase 3: 256-bit gather-expand ----
    const int g    = tid >> 6;    // 0..7  (group; frame slot within window)
    const int lane = tid & 63;    // 0..63 (32 B per lane -> 2048 B per frame)

    const float* __restrict__ fb = feat + (size_t)b * TT * DD + lane * 8;
    float* __restrict__ ob =
        out + ((size_t)b * MAX_LEN + base0 + g) * DD + lane * 8;

    // Frames handled by this thread: base0 + g + 8*j, j = 0..3.
    int idx[4];
#pragma unroll
    for (int j = 0; j < 4; j++)
        idx[j] = sidx[g + 8 * j];                     // SMEM broadcasts

    f32x8 val[4];
#pragma unroll
    for (int j = 0; j < 4; j++) {
        if (idx[j] >= 0) {
            val[j] = ldg256(fb + (size_t)idx[j] * DD);
        } else {
#pragma unroll
            for (int k = 0; k < 8; k++) val[j].v[k] = 0.f;
        }
    }

#pragma unroll
    for (int j = 0; j < 4; j++)
        stg256(ob + (size_t)8 * j * DD, val[j]);
}

// ---------------------------------------------------------------------------
// Launch
// ---------------------------------------------------------------------------
extern "C" void kernel_launch(void* const* d_in, const int* in_sizes, int n_in,
                              void* d_out, int out_size) {
    const float* feat = (const float*)d_in[0];   // features (8,512,512) f32
    const int*   dur  = (const int*)d_in[1];     // durations (8,512) i32
    float*       out  = (float*)d_out;           // (8,7680,512) f32

    (void)in_sizes; (void)n_in; (void)out_size;

    dim3 grid(MAX_LEN / FR, BB, 1);
    fused_expand_kernel<<<grid, 512>>>(feat, dur, out);
}